// round 13
// baseline (speedup 1.0000x reference)
#include <cuda_runtime.h>
#include <cuda_bf16.h>

#define IMG_H 4096
#define IMG_W 4096
#define OUT_H 4097
#define OUT_W 4097
#define TILE  32
#define HIST  35   // TILE + 3
#define INW   37   // HIST + 2 (sobel halo)
#define INP   38   // padded input row stride (words)
#define HP    37   // packed (mag|idx) row stride (odd)

__device__ __forceinline__ float4 f4add(float4 a, float4 b) {
    return make_float4(a.x + b.x, a.y + b.y, a.z + b.z, a.w + b.w);
}
__device__ __forceinline__ float4 f4addsub(float4 a, float4 p, float4 m) {
    return make_float4(a.x + p.x - m.x, a.y + p.y - m.y,
                       a.z + p.z - m.z, a.w + p.w - m.w);
}

// Sobel gradients -> packed (mag & ~7) | octant-bin
__device__ __forceinline__ unsigned int pack_pix(float dx, float dy)
{
    unsigned int sx = __float_as_uint(dx) >> 31;
    unsigned int sy = __float_as_uint(dy) >> 31;
    unsigned int tb = (fabsf(dy) > fabsf(dx)) ? 1u : 0u;
    unsigned int ex = sx ^ sy;
    unsigned int bi = (sy << 2) | (ex << 1) | (ex ^ tb);
    float m2  = fmaf(dx, dx, dy * dy);
    float mag = m2 * rsqrtf(fmaxf(m2, 1e-35f));
    return (__float_as_uint(mag) & 0xFFFFFFF8u) | bi;
}

__global__ __launch_bounds__(256, 5)
void sift_fused_kernel(const float* __restrict__ x, float* __restrict__ out)
{
    // rs: [chan-group][hist row][x] -> lane(x) contiguous float4
    __shared__ float4       s_rs[2][HIST][TILE];  // 35840 B (aliased as input tile)
    __shared__ unsigned int s_pk[HIST][HP];       //  5180 B packed mag|idx
    // total 41020 B -> 5 CTAs/SM

    float* s_in = (float*)s_rs;   // [INW][INP] = 5624 B, dead after stage 2

    const int X0   = blockIdx.x * TILE;
    const int Y0   = blockIdx.y * TILE;
    const int tid  = threadIdx.x;
    const int lane = tid & 31;
    const int wrow = tid >> 5;    // 0..7

    const bool interior =
        blockIdx.x >= 1 && blockIdx.x <= 126 &&
        blockIdx.y >= 1 && blockIdx.y <= 126;

    // ---- Stage 1: load input tile (origin Y0-3, X0-3) ----
    if (interior) {
        const float* src = x + (size_t)(Y0 - 3) * IMG_W + (X0 - 3);
        #pragma unroll
        for (int it = 0; it < 5; ++it) {
            int r = wrow + 8 * it;
            if (r < INW) {
                const float* row = src + (size_t)r * IMG_W;
                s_in[r * INP + lane] = row[lane];
                if (lane < INW - 32)
                    s_in[r * INP + 32 + lane] = row[32 + lane];
            }
        }
    } else {
        #pragma unroll
        for (int it = 0; it < 5; ++it) {
            int r = wrow + 8 * it;
            if (r < INW) {
                int  gy    = Y0 - 3 + r;
                bool rowok = (gy >= 0) && (gy < IMG_H);
                int  gx    = X0 - 3 + lane;
                float v = 0.0f;
                if (rowok && gx >= 0 && gx < IMG_W)
                    v = x[(size_t)gy * IMG_W + gx];
                s_in[r * INP + lane] = v;
                if (lane < INW - 32) {
                    int gx2 = gx + 32;
                    float v2 = 0.0f;
                    if (rowok && gx2 >= 0 && gx2 < IMG_W)
                        v2 = x[(size_t)gy * IMG_W + gx2];
                    s_in[r * INP + 32 + lane] = v2;
                }
            }
        }
    }
    __syncthreads();

    // ---- Stage 2: Sobel + octant bin, TWO vertically-adjacent pixels/thread ----
    // 18 row-pairs x 35 cols = 630 items; pair (h, h+1) shares 2 input rows.
    #pragma unroll
    for (int it = 0; it < 3; ++it) {
        int e = tid + 256 * it;
        if (e < 18 * 35) {
            int pr = e / 35;          // pair index 0..17
            int w  = e - pr * 35;     // column 0..34
            int h  = pr * 2;          // rows h and h+1 (h+1 skipped when ==35)
            const float* c = s_in + h * INP + w;

            float a00 = c[0],       a01 = c[1],         a02 = c[2];
            float a10 = c[INP],     a11 = c[INP + 1],   a12 = c[INP + 2];
            float a20 = c[2*INP],   a21 = c[2*INP + 1], a22 = c[2*INP + 2];
            float a30 = c[3*INP],   a31 = c[3*INP + 1], a32 = c[3*INP + 2];

            // pixel (h, w)
            float dx0 = (a02 - a00) + 2.0f * (a12 - a10) + (a22 - a20);
            float dy0 = (a20 - a00) + 2.0f * (a21 - a01) + (a22 - a02);
            unsigned int b0 = pack_pix(dx0, dy0);

            // pixel (h+1, w)
            float dx1 = (a12 - a10) + 2.0f * (a22 - a20) + (a32 - a30);
            float dy1 = (a30 - a10) + 2.0f * (a31 - a11) + (a32 - a12);
            unsigned int b1 = pack_pix(dx1, dy1);

            if (!interior) {
                int  gx  = X0 - 2 + w;
                bool cok = (gx >= 0) && (gx < IMG_W);
                int  gy0 = Y0 - 2 + h;
                if (!(cok && gy0 >= 0 && gy0 < IMG_H))     b0 = 0u;
                if (!(cok && gy0 + 1 >= 0 && gy0 + 1 < IMG_H)) b1 = 0u;
            }
            s_pk[h][w] = b0;
            if (h + 1 < HIST) s_pk[h + 1][w] = b1;
        }
    }
    __syncthreads();

    // ---- Stage 3: horizontal 4-tap row sums with one-hot scatter ----
    #pragma unroll
    for (int it = 0; it < 5; ++it) {
        int e = tid + 256 * it;
        if (e < HIST * TILE) {
            int h  = e >> 5;
            int ox = e & 31;
            float a0 = 0.f, a1 = 0.f, a2 = 0.f, a3 = 0.f;
            float a4 = 0.f, a5 = 0.f, a6 = 0.f, a7 = 0.f;
            #pragma unroll
            for (int k = 0; k < 4; k++) {
                unsigned int u = s_pk[h][ox + k];
                unsigned int i = u & 7u;
                float m = __uint_as_float(u);   // idx bits: <=2^-21 rel noise
                if (i == 0u) a0 += m;
                if (i == 1u) a1 += m;
                if (i == 2u) a2 += m;
                if (i == 3u) a3 += m;
                if (i == 4u) a4 += m;
                if (i == 5u) a5 += m;
                if (i == 6u) a6 += m;
                if (i == 7u) a7 += m;
            }
            s_rs[0][h][ox] = make_float4(a0, a1, a2, a3);
            s_rs[1][h][ox] = make_float4(a4, a5, a6, a7);
        }
    }
    __syncthreads();

    // ---- Stage 4: vertical 4-tap sliding sum + store 8 channels (champion) ----
    const int    gx    = X0 + lane;
    const size_t plane = (size_t)OUT_H * OUT_W;
    const int    oy0   = wrow * 4;          // 4 consecutive rows per thread

    float4 lo = f4add(f4add(s_rs[0][oy0][lane],     s_rs[0][oy0 + 1][lane]),
                      f4add(s_rs[0][oy0 + 2][lane], s_rs[0][oy0 + 3][lane]));
    float4 hi = f4add(f4add(s_rs[1][oy0][lane],     s_rs[1][oy0 + 1][lane]),
                      f4add(s_rs[1][oy0 + 2][lane], s_rs[1][oy0 + 3][lane]));

    #pragma unroll
    for (int r = 0; r < 4; r++) {
        if (r > 0) {
            lo = f4addsub(lo, s_rs[0][oy0 + r + 3][lane], s_rs[0][oy0 + r - 1][lane]);
            hi = f4addsub(hi, s_rs[1][oy0 + r + 3][lane], s_rs[1][oy0 + r - 1][lane]);
        }
        int gy = Y0 + oy0 + r;
        if (gy < OUT_H && gx < OUT_W) {
            size_t base = (size_t)gy * OUT_W + gx;
            out[0 * plane + base] = lo.x;
            out[1 * plane + base] = lo.y;
            out[2 * plane + base] = lo.z;
            out[3 * plane + base] = lo.w;
            out[4 * plane + base] = hi.x;
            out[5 * plane + base] = hi.y;
            out[6 * plane + base] = hi.z;
            out[7 * plane + base] = hi.w;
        }
    }
}

extern "C" void kernel_launch(void* const* d_in, const int* in_sizes, int n_in,
                              void* d_out, int out_size)
{
    const float* x   = (const float*)d_in[0];
    float*       out = (float*)d_out;
    dim3 grid((OUT_W + TILE - 1) / TILE, (OUT_H + TILE - 1) / TILE);  // 129 x 129
    sift_fused_kernel<<<grid, 256>>>(x, out);
}